// round 1
// baseline (speedup 1.0000x reference)
#include <cuda_runtime.h>

#define NMAX 50000
#define EMAX 1600000

// ---------------- static device scratch (allocation-free rule) ----------------
__device__ int   g_cnt[NMAX];
__device__ int   g_off[NMAX + 1];
__device__ int   g_cur[NMAX];
__device__ int2  g_epk[EMAX];          // (src, edge_id) per CSR slot
__device__ float g_q[NMAX * 64];
__device__ float g_k[NMAX * 64];
__device__ float g_v[NMAX * 64];
__device__ float g_agg[NMAX * 64];
__device__ float g_h[NMAX * 64];
__device__ float g_A[NMAX * 32];       // h @ Wem[0:64]
__device__ float g_B[NMAX * 32];       // h @ Wem[64:128]
__device__ float g_e[EMAX * 32];       // edge features (updated)
__device__ float g_bias[EMAX * 4];     // e @ We  (score bias, per layer)

// ---------------- CSR build ----------------
__global__ void k_zero(int n) {
    int i = blockIdx.x * blockDim.x + threadIdx.x;
    if (i < n) g_cnt[i] = 0;
}

__global__ void k_count(const int* __restrict__ dst, int e) {
    int i = blockIdx.x * blockDim.x + threadIdx.x;
    if (i < e) atomicAdd(&g_cnt[dst[i]], 1);
}

// single-block exclusive scan of g_cnt -> g_off (and g_cur copy)
__global__ void k_scan(int n) {
    __shared__ int sw[32];
    int t = threadIdx.x, lane = t & 31, w = t >> 5;
    int carry = 0;
    for (int base = 0; base < n; base += 1024) {
        int i = base + t;
        int v = (i < n) ? g_cnt[i] : 0;
        int x = v;
#pragma unroll
        for (int o = 1; o < 32; o <<= 1) {
            int y = __shfl_up_sync(0xffffffffu, x, o);
            if (lane >= o) x += y;
        }
        if (lane == 31) sw[w] = x;
        __syncthreads();
        if (t < 32) {
            int s = sw[t];
#pragma unroll
            for (int o = 1; o < 32; o <<= 1) {
                int y = __shfl_up_sync(0xffffffffu, s, o);
                if (t >= o) s += y;
            }
            sw[t] = s;
        }
        __syncthreads();
        int pref = (w > 0) ? sw[w - 1] : 0;
        int excl = carry + pref + x - v;
        if (i < n) { g_off[i] = excl; g_cur[i] = excl; }
        carry += sw[31];
        __syncthreads();
    }
    if (t == 0) g_off[n] = carry;
}

__global__ void k_scatter(const int* __restrict__ src, const int* __restrict__ dst, int e) {
    int i = blockIdx.x * blockDim.x + threadIdx.x;
    if (i >= e) return;
    int slot = atomicAdd(&g_cur[dst[i]], 1);
    g_epk[slot] = make_int2(src[i], i);
}

// insertion-sort each CSR segment by edge id -> fully deterministic accumulation order
__global__ void k_sortseg(int n) {
    int i = blockIdx.x * blockDim.x + threadIdx.x;
    if (i >= n) return;
    int b = g_off[i], ee = g_off[i + 1];
    for (int p = b + 1; p < ee; p++) {
        int2 key = g_epk[p];
        int q = p - 1;
        while (q >= b && g_epk[q].y > key.y) { g_epk[q + 1] = g_epk[q]; q--; }
        g_epk[q + 1] = key;
    }
}

// ---------------- layer-0 score bias: bias = e @ We[0]  ([E,32]x[32,4]) ----------------
__global__ void k_bias0(const float* __restrict__ ef, const float* __restrict__ We, int e) {
    __shared__ float sW[128];
    if (threadIdx.x < 128) sW[threadIdx.x] = We[threadIdx.x];
    __syncthreads();
    int id = blockIdx.x * blockDim.x + threadIdx.x;
    if (id >= e) return;
    const float4* ep = (const float4*)(ef + (size_t)id * 32);
    float4 b = make_float4(0.f, 0.f, 0.f, 0.f);
    const float4* wr = (const float4*)sW;  // wr[k] = We row k (4 heads)
#pragma unroll
    for (int i = 0; i < 8; i++) {
        float4 ev = __ldg(ep + i);
        float4 w0 = wr[4 * i], w1 = wr[4 * i + 1], w2 = wr[4 * i + 2], w3 = wr[4 * i + 3];
        b.x += ev.x * w0.x + ev.y * w1.x + ev.z * w2.x + ev.w * w3.x;
        b.y += ev.x * w0.y + ev.y * w1.y + ev.z * w2.y + ev.w * w3.y;
        b.z += ev.x * w0.z + ev.y * w1.z + ev.z * w2.z + ev.w * w3.z;
        b.w += ev.x * w0.w + ev.y * w1.w + ev.z * w2.w + ev.w * w3.w;
    }
    ((float4*)g_bias)[id] = b;
}

// ---------------- qkv projection: 4 rows/warp, W in smem ----------------
__global__ void k_proj(const float* __restrict__ hin, int useG,
                       const float* __restrict__ Wq, const float* __restrict__ Wk,
                       const float* __restrict__ Wv, int n) {
    __shared__ float sq[4096], sk[4096], sv[4096];
    int t = threadIdx.x;
    for (int i = t; i < 4096; i += 256) { sq[i] = Wq[i]; sk[i] = Wk[i]; sv[i] = Wv[i]; }
    __syncthreads();
    const float* h = useG ? g_h : hin;
    int lane = t & 31, w = t >> 5;
    int r0 = (blockIdx.x * 8 + w) * 4;
    float h0[4], h1[4];
#pragma unroll
    for (int r = 0; r < 4; r++) {
        int row = r0 + r;
        h0[r] = (row < n) ? h[row * 64 + lane] : 0.f;
        h1[r] = (row < n) ? h[row * 64 + lane + 32] : 0.f;
    }
    float aq0[4] = {0,0,0,0}, aq1[4] = {0,0,0,0};
    float ak0[4] = {0,0,0,0}, ak1[4] = {0,0,0,0};
    float av0[4] = {0,0,0,0}, av1[4] = {0,0,0,0};
#pragma unroll
    for (int j = 0; j < 32; j++) {
        float wq0 = sq[j * 64 + lane], wq1 = sq[j * 64 + lane + 32];
        float wk0 = sk[j * 64 + lane], wk1 = sk[j * 64 + lane + 32];
        float wv0 = sv[j * 64 + lane], wv1 = sv[j * 64 + lane + 32];
#pragma unroll
        for (int r = 0; r < 4; r++) {
            float hj = __shfl_sync(0xffffffffu, h0[r], j);
            aq0[r] += hj * wq0; aq1[r] += hj * wq1;
            ak0[r] += hj * wk0; ak1[r] += hj * wk1;
            av0[r] += hj * wv0; av1[r] += hj * wv1;
        }
    }
#pragma unroll
    for (int j = 0; j < 32; j++) {
        float wq0 = sq[(j + 32) * 64 + lane], wq1 = sq[(j + 32) * 64 + lane + 32];
        float wk0 = sk[(j + 32) * 64 + lane], wk1 = sk[(j + 32) * 64 + lane + 32];
        float wv0 = sv[(j + 32) * 64 + lane], wv1 = sv[(j + 32) * 64 + lane + 32];
#pragma unroll
        for (int r = 0; r < 4; r++) {
            float hj = __shfl_sync(0xffffffffu, h1[r], j);
            aq0[r] += hj * wq0; aq1[r] += hj * wq1;
            ak0[r] += hj * wk0; ak1[r] += hj * wk1;
            av0[r] += hj * wv0; av1[r] += hj * wv1;
        }
    }
#pragma unroll
    for (int r = 0; r < 4; r++) {
        int row = r0 + r;
        if (row >= n) break;
        g_q[row * 64 + lane] = aq0[r]; g_q[row * 64 + lane + 32] = aq1[r];
        g_k[row * 64 + lane] = ak0[r]; g_k[row * 64 + lane + 32] = ak1[r];
        g_v[row * 64 + lane] = av0[r]; g_v[row * 64 + lane + 32] = av1[r];
    }
}

// ---------------- attention: warp per dst node, online softmax, no atomics ----------------
__global__ void k_attn(int n) {
    int lane = threadIdx.x & 31;
    int node = blockIdx.x * 8 + (threadIdx.x >> 5);
    if (node >= n) return;
    int beg = g_off[node], end = g_off[node + 1];
    float q0 = g_q[node * 64 + lane] * 0.25f;        // 1/sqrt(dh)=0.25 folded in
    float q1 = g_q[node * 64 + lane + 32] * 0.25f;
    float m0 = -1e30f, m1 = -1e30f, dd0 = 0.f, dd1 = 0.f, acc0 = 0.f, acc1 = 0.f;
    int g = (lane >> 4) & 1;                          // headA = g, headB = 2+g
    int2 se = (beg < end) ? __ldg(&g_epk[beg]) : make_int2(0, 0);
    for (int p = beg; p < end; p++) {
        int2 cur = se;
        if (p + 1 < end) se = __ldg(&g_epk[p + 1]);
        const float* kr = g_k + (size_t)cur.x * 64;
        const float* vr = g_v + (size_t)cur.x * 64;
        float k0 = __ldg(kr + lane), k1 = __ldg(kr + lane + 32);
        float v0 = __ldg(vr + lane), v1 = __ldg(vr + lane + 32);
        float4 b = __ldg(((const float4*)g_bias) + cur.y);
        float p0 = q0 * k0, p1 = q1 * k1;
#pragma unroll
        for (int o = 8; o; o >>= 1) {
            p0 += __shfl_xor_sync(0xffffffffu, p0, o);
            p1 += __shfl_xor_sync(0xffffffffu, p1, o);
        }
        float sA = p0 + (g ? b.y : b.x);
        float sB = p1 + (g ? b.w : b.z);
        float mA = fmaxf(m0, sA), mB = fmaxf(m1, sB);
        float eA = __expf(sA - mA), eB = __expf(sB - mB);
        float cA = __expf(m0 - mA), cB = __expf(m1 - mB);
        dd0 = dd0 * cA + eA;       dd1 = dd1 * cB + eB;
        acc0 = acc0 * cA + eA * v0; acc1 = acc1 * cB + eB * v1;
        m0 = mA; m1 = mB;
    }
    g_agg[node * 64 + lane]      = acc0 / (dd0 + 1e-9f);
    g_agg[node * 64 + lane + 32] = acc1 / (dd1 + 1e-9f);
}

// ---------------- node update: h = LN(h + agg@Wo); fused A,B = h_new @ Wem[0:128] ----------------
__global__ void k_lnnode(const float* __restrict__ hin, int useGin,
                         const float* __restrict__ Wo, const float* __restrict__ gn,
                         const float* __restrict__ bn, const float* __restrict__ Wab,
                         float* __restrict__ outp, int useOut, int doAB, int n) {
    __shared__ float sWo[4096];
    __shared__ float sAB[4096];
    for (int i = threadIdx.x; i < 4096; i += 256) {
        sWo[i] = Wo[i];
        if (doAB) sAB[i] = Wab[i];
    }
    __syncthreads();
    int lane = threadIdx.x & 31, w = threadIdx.x >> 5;
    int row = blockIdx.x * 8 + w;
    if (row >= n) return;
    const float* h = useGin ? g_h : hin;
    float a0 = g_agg[row * 64 + lane], a1 = g_agg[row * 64 + lane + 32];
    float o0 = 0.f, o1 = 0.f;
#pragma unroll
    for (int j = 0; j < 32; j++) {
        float aj = __shfl_sync(0xffffffffu, a0, j);
        o0 += aj * sWo[j * 64 + lane];
        o1 += aj * sWo[j * 64 + lane + 32];
    }
#pragma unroll
    for (int j = 0; j < 32; j++) {
        float aj = __shfl_sync(0xffffffffu, a1, j);
        o0 += aj * sWo[(j + 32) * 64 + lane];
        o1 += aj * sWo[(j + 32) * 64 + lane + 32];
    }
    float x0 = h[row * 64 + lane] + o0;
    float x1 = h[row * 64 + lane + 32] + o1;
    float s = x0 + x1;
#pragma unroll
    for (int o = 16; o; o >>= 1) s += __shfl_xor_sync(0xffffffffu, s, o);
    float mu = s * (1.f / 64.f);
    float d0 = x0 - mu, d1 = x1 - mu;
    float vs = d0 * d0 + d1 * d1;
#pragma unroll
    for (int o = 16; o; o >>= 1) vs += __shfl_xor_sync(0xffffffffu, vs, o);
    float inv = rsqrtf(vs * (1.f / 64.f) + 1e-5f);
    float y0 = d0 * inv * __ldg(gn + lane) + __ldg(bn + lane);
    float y1 = d1 * inv * __ldg(gn + lane + 32) + __ldg(bn + lane + 32);
    float* hp = useOut ? outp : g_h;
    hp[row * 64 + lane] = y0;
    hp[row * 64 + lane + 32] = y1;
    if (doAB) {
        float A = 0.f, B = 0.f;
#pragma unroll
        for (int j = 0; j < 32; j++) {
            float yj = __shfl_sync(0xffffffffu, y0, j);
            A += yj * sAB[j * 32 + lane];
            B += yj * sAB[(j + 64) * 32 + lane];
        }
#pragma unroll
        for (int j = 0; j < 32; j++) {
            float yj = __shfl_sync(0xffffffffu, y1, j);
            A += yj * sAB[(j + 32) * 32 + lane];
            B += yj * sAB[(j + 96) * 32 + lane];
        }
        g_A[row * 32 + lane] = A;
        g_B[row * 32 + lane] = B;
    }
}

// ---------------- edge update: e = LN(e + gelu(A[src]+B[dst]+e@Wem2+bem)); fused next bias ----------------
__global__ void k_edge(const float* __restrict__ ein, int useGE,
                       const float* __restrict__ Wem2, const float* __restrict__ bem,
                       const float* __restrict__ ge, const float* __restrict__ be,
                       const float* __restrict__ WeN,
                       const int* __restrict__ src, const int* __restrict__ dstp, int e) {
    __shared__ float sW[1024];
    __shared__ float sWeN[128];
    __shared__ float sbem[32], sge[32], sbe[32];
    int t = threadIdx.x;
    for (int i = t; i < 1024; i += 128) sW[i] = Wem2[i];
    if (t < 128) sWeN[t] = WeN[t];
    if (t < 32) { sbem[t] = bem[t]; sge[t] = ge[t]; sbe[t] = be[t]; }
    __syncthreads();
    int id = blockIdx.x * 128 + t;
    if (id >= e) return;
    const float* ebase = useGE ? (const float*)g_e : ein;
    float er[32];
    const float4* ep = (const float4*)(ebase + (size_t)id * 32);
#pragma unroll
    for (int i = 0; i < 8; i++) {
        float4 v = __ldg(ep + i);
        er[4 * i] = v.x; er[4 * i + 1] = v.y; er[4 * i + 2] = v.z; er[4 * i + 3] = v.w;
    }
    int s = __ldg(src + id), d2 = __ldg(dstp + id);
    float acc[32];
    const float4* Ar = (const float4*)(g_A + (size_t)s * 32);
    const float4* Br = (const float4*)(g_B + (size_t)d2 * 32);
#pragma unroll
    for (int i = 0; i < 8; i++) {
        float4 a = __ldg(Ar + i), b = __ldg(Br + i);
        acc[4 * i]     = a.x + b.x + sbem[4 * i];
        acc[4 * i + 1] = a.y + b.y + sbem[4 * i + 1];
        acc[4 * i + 2] = a.z + b.z + sbem[4 * i + 2];
        acc[4 * i + 3] = a.w + b.w + sbem[4 * i + 3];
    }
#pragma unroll
    for (int k = 0; k < 32; k++) {
        float ek = er[k];
        const float4* wr = (const float4*)(sW + k * 32);
#pragma unroll
        for (int j = 0; j < 8; j++) {
            float4 ww = wr[j];
            acc[4 * j]     += ek * ww.x;
            acc[4 * j + 1] += ek * ww.y;
            acc[4 * j + 2] += ek * ww.z;
            acc[4 * j + 3] += ek * ww.w;
        }
    }
    // tanh-gelu (matches jax.nn.gelu approximate=True) + residual
    float mu = 0.f;
#pragma unroll
    for (int j = 0; j < 32; j++) {
        float u = acc[j];
        float z = 0.7978845608028654f * (u + 0.044715f * u * u * u);
        float th = 1.f - 2.f / (__expf(2.f * z) + 1.f);
        float x = er[j] + 0.5f * u * (1.f + th);
        acc[j] = x;
        mu += x;
    }
    mu *= (1.f / 32.f);
    float var = 0.f;
#pragma unroll
    for (int j = 0; j < 32; j++) { float dx = acc[j] - mu; var += dx * dx; }
    float inv = rsqrtf(var * (1.f / 32.f) + 1e-5f);
    float4 bb = make_float4(0.f, 0.f, 0.f, 0.f);
#pragma unroll
    for (int j = 0; j < 32; j++) {
        float y = (acc[j] - mu) * inv * sge[j] + sbe[j];
        acc[j] = y;
        float4 wv = *(const float4*)(sWeN + j * 4);
        bb.x += y * wv.x; bb.y += y * wv.y; bb.z += y * wv.z; bb.w += y * wv.w;
    }
    float4* op = (float4*)(g_e + (size_t)id * 32);
#pragma unroll
    for (int i = 0; i < 8; i++)
        op[i] = make_float4(acc[4 * i], acc[4 * i + 1], acc[4 * i + 2], acc[4 * i + 3]);
    ((float4*)g_bias)[id] = bb;    // bias for the NEXT layer
}

// ---------------- launch ----------------
extern "C" void kernel_launch(void* const* d_in, const int* in_sizes, int n_in,
                              void* d_out, int out_size) {
    const float* nodef = (const float*)d_in[0];
    const float* edgef = (const float*)d_in[1];
    const int*   ei    = (const int*)d_in[2];
    const float* Wq    = (const float*)d_in[3];
    const float* Wk    = (const float*)d_in[4];
    const float* Wv    = (const float*)d_in[5];
    const float* Wo    = (const float*)d_in[6];
    const float* We    = (const float*)d_in[7];
    const float* Wem   = (const float*)d_in[8];
    const float* bem   = (const float*)d_in[9];
    const float* gn    = (const float*)d_in[10];
    const float* bn    = (const float*)d_in[11];
    const float* ge    = (const float*)d_in[12];
    const float* be    = (const float*)d_in[13];
    float* out = (float*)d_out;

    int n = in_sizes[0] / 64;
    int e = in_sizes[1] / 32;
    const int* src = ei;
    const int* dst = ei + e;

    // CSR (deterministic: segments sorted by edge id)
    k_zero<<<(n + 255) / 256, 256>>>(n);
    k_count<<<(e + 255) / 256, 256>>>(dst, e);
    k_scan<<<1, 1024>>>(n);
    k_scatter<<<(e + 255) / 256, 256>>>(src, dst, e);
    k_sortseg<<<(n + 127) / 128, 128>>>(n);

    // layer-0 score bias
    k_bias0<<<(e + 127) / 128, 128>>>(edgef, We, e);

    for (int i = 0; i < 3; i++) {
        int useG = (i > 0);
        k_proj<<<(n + 31) / 32, 256>>>(nodef, useG,
                                       Wq + i * 4096, Wk + i * 4096, Wv + i * 4096, n);
        k_attn<<<(n + 7) / 8, 256>>>(n);
        int last = (i == 2);
        k_lnnode<<<(n + 7) / 8, 256>>>(nodef, useG,
                                       Wo + i * 4096, gn + i * 64, bn + i * 64,
                                       Wem + i * 5120, out, last, !last, n);
        if (!last) {
            // edge update + fused bias for layer i+1
            k_edge<<<(e + 127) / 128, 128>>>(edgef, (i > 0),
                                             Wem + i * 5120 + 4096, bem + i * 32,
                                             ge + i * 32, be + i * 32,
                                             We + (i + 1) * 128,
                                             src, dst, e);
        }
    }
}

// round 2
// speedup vs baseline: 1.0129x; 1.0129x over previous
#include <cuda_runtime.h>

#define NMAX 50000
#define EMAX 1600000

// ---------------- static device scratch (allocation-free rule) ----------------
__device__ int   g_cnt[NMAX];
__device__ int   g_off[NMAX + 1];
__device__ int   g_cur[NMAX];
__device__ int   g_epk[EMAX];          // src node per CSR slot
__device__ int   g_slot[EMAX];         // edge id -> CSR slot
__device__ float g_q[NMAX * 64];
__device__ float g_k[NMAX * 64];
__device__ float g_v[NMAX * 64];
__device__ float g_agg[NMAX * 64];
__device__ float g_h[NMAX * 64];
__device__ float g_A[NMAX * 32];       // h @ Wem[0:64]
__device__ float g_B[NMAX * 32];       // h @ Wem[64:128]
__device__ float g_e[EMAX * 32];       // edge features (layer-0 output only)
__device__ float g_bias[EMAX * 4];     // score bias, stored in CSR-slot order

// ---------------- CSR build ----------------
__global__ void k_zero(int n) {
    int i = blockIdx.x * blockDim.x + threadIdx.x;
    if (i < n) g_cnt[i] = 0;
}

__global__ void k_count(const int* __restrict__ dst, int e) {
    int i = blockIdx.x * blockDim.x + threadIdx.x;
    if (i < e) atomicAdd(&g_cnt[dst[i]], 1);
}

// single-block exclusive scan of g_cnt -> g_off (and g_cur copy)
__global__ void k_scan(int n) {
    __shared__ int sw[32];
    int t = threadIdx.x, lane = t & 31, w = t >> 5;
    int carry = 0;
    for (int base = 0; base < n; base += 1024) {
        int i = base + t;
        int v = (i < n) ? g_cnt[i] : 0;
        int x = v;
#pragma unroll
        for (int o = 1; o < 32; o <<= 1) {
            int y = __shfl_up_sync(0xffffffffu, x, o);
            if (lane >= o) x += y;
        }
        if (lane == 31) sw[w] = x;
        __syncthreads();
        if (t < 32) {
            int s = sw[t];
#pragma unroll
            for (int o = 1; o < 32; o <<= 1) {
                int y = __shfl_up_sync(0xffffffffu, s, o);
                if (t >= o) s += y;
            }
            sw[t] = s;
        }
        __syncthreads();
        int pref = (w > 0) ? sw[w - 1] : 0;
        int excl = carry + pref + x - v;
        if (i < n) { g_off[i] = excl; g_cur[i] = excl; }
        carry += sw[31];
        __syncthreads();
    }
    if (t == 0) g_off[n] = carry;
}

__global__ void k_scatter(const int* __restrict__ src, const int* __restrict__ dst, int e) {
    int i = blockIdx.x * blockDim.x + threadIdx.x;
    if (i >= e) return;
    int slot = atomicAdd(&g_cur[dst[i]], 1);
    g_epk[slot] = src[i];
    g_slot[i] = slot;
}

// ---------------- layer-0 score bias: bias[slot] = e @ We[0] ----------------
// warp-cooperative coalesced staging: 4 warps/block, 32 edges/warp
__global__ void k_bias0(const float* __restrict__ ef, const float* __restrict__ We, int e) {
    __shared__ float sW[128];
    __shared__ float buf[4][32 * 33];
    int t = threadIdx.x;
    if (t < 128) sW[t] = We[t];
    __syncthreads();
    int w = t >> 5, lane = t & 31;
    int base = (blockIdx.x * 4 + w) * 32;
    float* b = buf[w];
#pragma unroll 4
    for (int j = 0; j < 32; j++) {
        int ed = base + j;
        b[j * 33 + lane] = (ed < e) ? __ldg(ef + (size_t)ed * 32 + lane) : 0.f;
    }
    __syncwarp();
    int ed0 = base + lane;
    if (ed0 >= e) return;
    float4 bb = make_float4(0.f, 0.f, 0.f, 0.f);
#pragma unroll
    for (int k = 0; k < 32; k++) {
        float ek = b[lane * 33 + k];
        float4 wv = *(const float4*)(sW + k * 4);
        bb.x += ek * wv.x; bb.y += ek * wv.y; bb.z += ek * wv.z; bb.w += ek * wv.w;
    }
    int slot = g_slot[ed0];
    ((float4*)g_bias)[slot] = bb;
}

// ---------------- qkv projection: 4 rows/warp, W in smem ----------------
__global__ void k_proj(const float* __restrict__ hin, int useG,
                       const float* __restrict__ Wq, const float* __restrict__ Wk,
                       const float* __restrict__ Wv, int n) {
    __shared__ float sq[4096], sk[4096], sv[4096];
    int t = threadIdx.x;
    for (int i = t; i < 4096; i += 256) { sq[i] = Wq[i]; sk[i] = Wk[i]; sv[i] = Wv[i]; }
    __syncthreads();
    const float* h = useG ? g_h : hin;
    int lane = t & 31, w = t >> 5;
    int r0 = (blockIdx.x * 8 + w) * 4;
    float h0[4], h1[4];
#pragma unroll
    for (int r = 0; r < 4; r++) {
        int row = r0 + r;
        h0[r] = (row < n) ? h[row * 64 + lane] : 0.f;
        h1[r] = (row < n) ? h[row * 64 + lane + 32] : 0.f;
    }
    float aq0[4] = {0,0,0,0}, aq1[4] = {0,0,0,0};
    float ak0[4] = {0,0,0,0}, ak1[4] = {0,0,0,0};
    float av0[4] = {0,0,0,0}, av1[4] = {0,0,0,0};
#pragma unroll
    for (int j = 0; j < 32; j++) {
        float wq0 = sq[j * 64 + lane], wq1 = sq[j * 64 + lane + 32];
        float wk0 = sk[j * 64 + lane], wk1 = sk[j * 64 + lane + 32];
        float wv0 = sv[j * 64 + lane], wv1 = sv[j * 64 + lane + 32];
#pragma unroll
        for (int r = 0; r < 4; r++) {
            float hj = __shfl_sync(0xffffffffu, h0[r], j);
            aq0[r] += hj * wq0; aq1[r] += hj * wq1;
            ak0[r] += hj * wk0; ak1[r] += hj * wk1;
            av0[r] += hj * wv0; av1[r] += hj * wv1;
        }
    }
#pragma unroll
    for (int j = 0; j < 32; j++) {
        float wq0 = sq[(j + 32) * 64 + lane], wq1 = sq[(j + 32) * 64 + lane + 32];
        float wk0 = sk[(j + 32) * 64 + lane], wk1 = sk[(j + 32) * 64 + lane + 32];
        float wv0 = sv[(j + 32) * 64 + lane], wv1 = sv[(j + 32) * 64 + lane + 32];
#pragma unroll
        for (int r = 0; r < 4; r++) {
            float hj = __shfl_sync(0xffffffffu, h1[r], j);
            aq0[r] += hj * wq0; aq1[r] += hj * wq1;
            ak0[r] += hj * wk0; ak1[r] += hj * wk1;
            av0[r] += hj * wv0; av1[r] += hj * wv1;
        }
    }
#pragma unroll
    for (int r = 0; r < 4; r++) {
        int row = r0 + r;
        if (row >= n) break;
        g_q[row * 64 + lane] = aq0[r]; g_q[row * 64 + lane + 32] = aq1[r];
        g_k[row * 64 + lane] = ak0[r]; g_k[row * 64 + lane + 32] = ak1[r];
        g_v[row * 64 + lane] = av0[r]; g_v[row * 64 + lane + 32] = av1[r];
    }
}

// ---------------- attention: warp per dst node, online softmax, pipelined loads ----------------
__global__ void k_attn(int n) {
    int lane = threadIdx.x & 31;
    int node = blockIdx.x * 8 + (threadIdx.x >> 5);
    if (node >= n) return;
    int beg = g_off[node], end = g_off[node + 1];
    float q0 = g_q[node * 64 + lane] * 0.25f;        // 1/sqrt(dh)=0.25 folded in
    float q1 = g_q[node * 64 + lane + 32] * 0.25f;
    float m0 = -1e30f, m1 = -1e30f, dd0 = 0.f, dd1 = 0.f, acc0 = 0.f, acc1 = 0.f;
    int g = (lane >> 4) & 1;                          // headA = g, headB = 2+g
    float k0n = 0.f, k1n = 0.f, v0n = 0.f, v1n = 0.f;
    float4 bn_ = make_float4(0.f, 0.f, 0.f, 0.f);
    if (beg < end) {
        int s = __ldg(&g_epk[beg]);
        const float* kr = g_k + (size_t)s * 64;
        const float* vr = g_v + (size_t)s * 64;
        k0n = __ldg(kr + lane); k1n = __ldg(kr + lane + 32);
        v0n = __ldg(vr + lane); v1n = __ldg(vr + lane + 32);
        bn_ = __ldg(((const float4*)g_bias) + beg);
    }
    for (int p = beg; p < end; p++) {
        float k0 = k0n, k1 = k1n, v0 = v0n, v1 = v1n;
        float4 b = bn_;
        if (p + 1 < end) {
            int s = __ldg(&g_epk[p + 1]);
            const float* kr = g_k + (size_t)s * 64;
            const float* vr = g_v + (size_t)s * 64;
            k0n = __ldg(kr + lane); k1n = __ldg(kr + lane + 32);
            v0n = __ldg(vr + lane); v1n = __ldg(vr + lane + 32);
            bn_ = __ldg(((const float4*)g_bias) + (p + 1));
        }
        float p0 = q0 * k0, p1 = q1 * k1;
#pragma unroll
        for (int o = 8; o; o >>= 1) {
            p0 += __shfl_xor_sync(0xffffffffu, p0, o);
            p1 += __shfl_xor_sync(0xffffffffu, p1, o);
        }
        float sA = p0 + (g ? b.y : b.x);
        float sB = p1 + (g ? b.w : b.z);
        float mA = fmaxf(m0, sA), mB = fmaxf(m1, sB);
        float eA = __expf(sA - mA), eB = __expf(sB - mB);
        float cA = __expf(m0 - mA), cB = __expf(m1 - mB);
        dd0 = dd0 * cA + eA;        dd1 = dd1 * cB + eB;
        acc0 = acc0 * cA + eA * v0; acc1 = acc1 * cB + eB * v1;
        m0 = mA; m1 = mB;
    }
    g_agg[node * 64 + lane]      = acc0 / (dd0 + 1e-9f);
    g_agg[node * 64 + lane + 32] = acc1 / (dd1 + 1e-9f);
}

// ---------------- node update: h = LN(h + agg@Wo); fused A,B = h_new @ Wem[0:128] ----------------
__global__ void k_lnnode(const float* __restrict__ hin, int useGin,
                         const float* __restrict__ Wo, const float* __restrict__ gn,
                         const float* __restrict__ bn, const float* __restrict__ Wab,
                         float* __restrict__ outp, int useOut, int doAB, int n) {
    __shared__ float sWo[4096];
    __shared__ float sAB[4096];
    for (int i = threadIdx.x; i < 4096; i += 256) {
        sWo[i] = Wo[i];
        if (doAB) sAB[i] = Wab[i];
    }
    __syncthreads();
    int lane = threadIdx.x & 31, w = threadIdx.x >> 5;
    int row = blockIdx.x * 8 + w;
    if (row >= n) return;
    const float* h = useGin ? g_h : hin;
    float a0 = g_agg[row * 64 + lane], a1 = g_agg[row * 64 + lane + 32];
    float o0 = 0.f, o1 = 0.f;
#pragma unroll
    for (int j = 0; j < 32; j++) {
        float aj = __shfl_sync(0xffffffffu, a0, j);
        o0 += aj * sWo[j * 64 + lane];
        o1 += aj * sWo[j * 64 + lane + 32];
    }
#pragma unroll
    for (int j = 0; j < 32; j++) {
        float aj = __shfl_sync(0xffffffffu, a1, j);
        o0 += aj * sWo[(j + 32) * 64 + lane];
        o1 += aj * sWo[(j + 32) * 64 + lane + 32];
    }
    float x0 = h[row * 64 + lane] + o0;
    float x1 = h[row * 64 + lane + 32] + o1;
    float s = x0 + x1;
#pragma unroll
    for (int o = 16; o; o >>= 1) s += __shfl_xor_sync(0xffffffffu, s, o);
    float mu = s * (1.f / 64.f);
    float d0 = x0 - mu, d1 = x1 - mu;
    float vs = d0 * d0 + d1 * d1;
#pragma unroll
    for (int o = 16; o; o >>= 1) vs += __shfl_xor_sync(0xffffffffu, vs, o);
    float inv = rsqrtf(vs * (1.f / 64.f) + 1e-5f);
    float y0 = d0 * inv * __ldg(gn + lane) + __ldg(bn + lane);
    float y1 = d1 * inv * __ldg(gn + lane + 32) + __ldg(bn + lane + 32);
    float* hp = useOut ? outp : g_h;
    hp[row * 64 + lane] = y0;
    hp[row * 64 + lane + 32] = y1;
    if (doAB) {
        float A = 0.f, B = 0.f;
#pragma unroll
        for (int j = 0; j < 32; j++) {
            float yj = __shfl_sync(0xffffffffu, y0, j);
            A += yj * sAB[j * 32 + lane];
            B += yj * sAB[(j + 64) * 32 + lane];
        }
#pragma unroll
        for (int j = 0; j < 32; j++) {
            float yj = __shfl_sync(0xffffffffu, y1, j);
            A += yj * sAB[(j + 32) * 32 + lane];
            B += yj * sAB[(j + 96) * 32 + lane];
        }
        g_A[row * 32 + lane] = A;
        g_B[row * 32 + lane] = B;
    }
}

// ---------------- edge update: coalesced smem staging, thread-per-edge compute ----------------
// e_new = LN(e + gelu(A[src]+B[dst]+e@Wem2+bem)); emits next-layer bias (slot order).
// storeE=0 on the last edge layer (e_new only feeds the bias).
__global__ void k_edge(const float* __restrict__ ein, int useGE,
                       const float* __restrict__ Wem2, const float* __restrict__ bem,
                       const float* __restrict__ ge, const float* __restrict__ be,
                       const float* __restrict__ WeN,
                       const int* __restrict__ src, const int* __restrict__ dstp,
                       int e, int storeE) {
    __shared__ float sW[1024];
    __shared__ float sWeN[128];
    __shared__ float sbem[32], sge[32], sbe[32];
    __shared__ float buf[4][32 * 33];
    int t = threadIdx.x;
    for (int i = t; i < 1024; i += 128) sW[i] = Wem2[i];
    if (t < 128) sWeN[t] = WeN[t];
    if (t < 32) { sbem[t] = bem[t]; sge[t] = ge[t]; sbe[t] = be[t]; }
    __syncthreads();
    int w = t >> 5, lane = t & 31;
    int base = (blockIdx.x * 4 + w) * 32;
    float* b = buf[w];
    const float* ebase = useGE ? (const float*)g_e : ein;

    // stage e rows (coalesced)
#pragma unroll 4
    for (int j = 0; j < 32; j++) {
        int ed = base + j;
        b[j * 33 + lane] = (ed < e) ? __ldg(ebase + (size_t)ed * 32 + lane) : 0.f;
    }
    __syncwarp();
    float er[32];
#pragma unroll
    for (int k = 0; k < 32; k++) er[k] = b[lane * 33 + k];
    __syncwarp();

    int ed0 = base + lane;
    int s_l = (ed0 < e) ? __ldg(src + ed0)  : 0;
    int d_l = (ed0 < e) ? __ldg(dstp + ed0) : 0;

    // stage A[src] rows (coalesced gathers: 1 line per row)
#pragma unroll 4
    for (int j = 0; j < 32; j++) {
        int sj = __shfl_sync(0xffffffffu, s_l, j);
        b[j * 33 + lane] = __ldg(g_A + (size_t)sj * 32 + lane);
    }
    __syncwarp();
    float acc[32];
#pragma unroll
    for (int k = 0; k < 32; k++) acc[k] = b[lane * 33 + k] + sbem[k];
    __syncwarp();

    // stage B[dst] rows
#pragma unroll 4
    for (int j = 0; j < 32; j++) {
        int dj = __shfl_sync(0xffffffffu, d_l, j);
        b[j * 33 + lane] = __ldg(g_B + (size_t)dj * 32 + lane);
    }
    __syncwarp();
#pragma unroll
    for (int k = 0; k < 32; k++) acc[k] += b[lane * 33 + k];
    __syncwarp();

    // e @ Wem2 (W rows broadcast from smem)
#pragma unroll
    for (int k = 0; k < 32; k++) {
        float ek = er[k];
        const float4* wr = (const float4*)(sW + k * 32);
#pragma unroll
        for (int j = 0; j < 8; j++) {
            float4 ww = wr[j];
            acc[4 * j]     += ek * ww.x;
            acc[4 * j + 1] += ek * ww.y;
            acc[4 * j + 2] += ek * ww.z;
            acc[4 * j + 3] += ek * ww.w;
        }
    }

    // tanh-gelu + residual + LN (in registers)
    float mu = 0.f;
#pragma unroll
    for (int j = 0; j < 32; j++) {
        float u = acc[j];
        float z = 0.7978845608028654f * (u + 0.044715f * u * u * u);
        float th = 1.f - 2.f / (__expf(2.f * z) + 1.f);
        float x = er[j] + 0.5f * u * (1.f + th);
        acc[j] = x;
        mu += x;
    }
    mu *= (1.f / 32.f);
    float var = 0.f;
#pragma unroll
    for (int j = 0; j < 32; j++) { float dx = acc[j] - mu; var += dx * dx; }
    float inv = rsqrtf(var * (1.f / 32.f) + 1e-5f);
    float4 bb = make_float4(0.f, 0.f, 0.f, 0.f);
#pragma unroll
    for (int j = 0; j < 32; j++) {
        float y = (acc[j] - mu) * inv * sge[j] + sbe[j];
        acc[j] = y;
        float4 wv = *(const float4*)(sWeN + j * 4);
        bb.x += y * wv.x; bb.y += y * wv.y; bb.z += y * wv.z; bb.w += y * wv.w;
    }
    if (ed0 < e) {
        int slot = __ldg(g_slot + ed0);
        ((float4*)g_bias)[slot] = bb;    // bias for the NEXT layer (slot order)
    }
    if (storeE) {
        __syncwarp();
#pragma unroll
        for (int k = 0; k < 32; k++) b[lane * 33 + k] = acc[k];
        __syncwarp();
#pragma unroll 4
        for (int j = 0; j < 32; j++) {
            int ed = base + j;
            if (ed < e) g_e[(size_t)ed * 32 + lane] = b[j * 33 + lane];
        }
    }
}

// ---------------- launch ----------------
extern "C" void kernel_launch(void* const* d_in, const int* in_sizes, int n_in,
                              void* d_out, int out_size) {
    const float* nodef = (const float*)d_in[0];
    const float* edgef = (const float*)d_in[1];
    const int*   ei    = (const int*)d_in[2];
    const float* Wq    = (const float*)d_in[3];
    const float* Wk    = (const float*)d_in[4];
    const float* Wv    = (const float*)d_in[5];
    const float* Wo    = (const float*)d_in[6];
    const float* We    = (const float*)d_in[7];
    const float* Wem   = (const float*)d_in[8];
    const float* bem   = (const float*)d_in[9];
    const float* gn    = (const float*)d_in[10];
    const float* bn    = (const float*)d_in[11];
    const float* ge    = (const float*)d_in[12];
    const float* be    = (const float*)d_in[13];
    float* out = (float*)d_out;

    int n = in_sizes[0] / 64;
    int e = in_sizes[1] / 32;
    const int* src = ei;
    const int* dst = ei + e;

    // CSR (order within segment = atomic arrival; fp-tolerance covers reorder)
    k_zero<<<(n + 255) / 256, 256>>>(n);
    k_count<<<(e + 255) / 256, 256>>>(dst, e);
    k_scan<<<1, 1024>>>(n);
    k_scatter<<<(e + 255) / 256, 256>>>(src, dst, e);

    // layer-0 score bias
    k_bias0<<<(e + 127) / 128, 128>>>(edgef, We, e);

    for (int i = 0; i < 3; i++) {
        int useG = (i > 0);
        k_proj<<<(n + 31) / 32, 256>>>(nodef, useG,
                                       Wq + i * 4096, Wk + i * 4096, Wv + i * 4096, n);
        k_attn<<<(n + 7) / 8, 256>>>(n);
        int last = (i == 2);
        k_lnnode<<<(n + 7) / 8, 256>>>(nodef, useG,
                                       Wo + i * 4096, gn + i * 64, bn + i * 64,
                                       Wem + i * 5120, out, last, !last, n);
        if (!last) {
            // edge update + fused bias for layer i+1; store e only after layer 0
            k_edge<<<(e + 127) / 128, 128>>>(edgef, (i > 0),
                                             Wem + i * 5120 + 4096, bem + i * 32,
                                             ge + i * 32, be + i * 32,
                                             We + (i + 1) * 128,
                                             src, dst, e, (i == 0) ? 1 : 0);
        }
    }
}